// round 1
// baseline (speedup 1.0000x reference)
#include <cuda_runtime.h>

// Net_32521492365587 — tiny LSTM ensemble + dense decode, single output scalar.
//
// Inputs (metadata order):
//  0: x        (1,1,8)        8
//  1: h0_gen   (10,10)        100
//  2: c0_gen   (10,10)        100
//  3: W_ih_opp (200,8)        1600
//  4: W_hh_opp (200,50)       10000   [UNUSED: multiplied by zero state]
//  5: b_ih_opp (200,)         200
//  6: b_hh_opp (200,)         200
//  7: W_ih_gen (10,40,8)      3200
//  8: W_hh_gen (10,40,10)     4000
//  9: b_ih_gen (10,40)        400
// 10: b_hh_gen (10,40)        400
// 11: W1       (75,150)       11250
// 12: b1       (75,)          75
// 13: W2       (1,75)         75
// 14: b2       (1,)           1
// out: (1,1,1) float32

__device__ __forceinline__ float sigmoidf_(float v) {
    return 1.0f / (1.0f + __expf(-v));
}

__global__ __launch_bounds__(256, 1)
void net_kernel(const float* __restrict__ x,
                const float* __restrict__ h0_gen,
                const float* __restrict__ c0_gen,
                const float* __restrict__ W_ih_opp,
                const float* __restrict__ b_ih_opp,
                const float* __restrict__ b_hh_opp,
                const float* __restrict__ W_ih_gen,
                const float* __restrict__ W_hh_gen,
                const float* __restrict__ b_ih_gen,
                const float* __restrict__ b_hh_gen,
                const float* __restrict__ W1,
                const float* __restrict__ b1,
                const float* __restrict__ W2,
                const float* __restrict__ b2,
                float* __restrict__ out)
{
    __shared__ float s_x[8];
    __shared__ float s_h0[100];
    __shared__ float s_c0[100];
    __shared__ float s_go[200];   // opp gate pre-activations
    __shared__ float s_gg[400];   // gen gate pre-activations
    __shared__ float s_feat[150]; // [h_gen (100) | h_opp (50)]
    __shared__ float s_hid[75];

    const int tid = threadIdx.x;

    // ---- stage tiny vectors into shared ----
    if (tid < 8)                    s_x[tid]        = x[tid];
    if (tid >= 32  && tid < 132)    s_h0[tid - 32]  = h0_gen[tid - 32];
    if (tid >= 132 && tid < 232)    s_c0[tid - 132] = c0_gen[tid - 132];
    __syncthreads();

    // ---- phase 1: 600 gate pre-activations (200 opp + 400 gen) ----
    // opp LSTM runs from zero state, so W_hh_opp @ h == 0: skip that 40KB read.
    for (int idx = tid; idx < 600; idx += 256) {
        if (idx < 200) {
            const float* __restrict__ w = W_ih_opp + idx * 8;
            float acc = b_ih_opp[idx] + b_hh_opp[idx];
            #pragma unroll
            for (int i = 0; i < 8; ++i) acc = fmaf(w[i], s_x[i], acc);
            s_go[idx] = acc;
        } else {
            const int gg = idx - 200;          // 0..399
            const int g  = gg / 40;            // gen cell 0..9
            const float* __restrict__ wi = W_ih_gen + gg * 8;
            const float* __restrict__ wh = W_hh_gen + gg * 10;
            const float* __restrict__ h0 = s_h0 + g * 10;
            float acc = b_ih_gen[gg] + b_hh_gen[gg];
            #pragma unroll
            for (int i = 0; i < 8; ++i)  acc = fmaf(wi[i], s_x[i], acc);
            #pragma unroll
            for (int i = 0; i < 10; ++i) acc = fmaf(wh[i], h0[i], acc);
            s_gg[gg] = acc;
        }
    }
    __syncthreads();

    // ---- phase 2: activations -> feat (gate order i,f,g,o) ----
    if (tid < 50) {
        // opp: c0 = 0 -> c2 = sig(i)*tanh(g); h = sig(o)*tanh(c2)
        const float gi = s_go[tid];
        const float gc = s_go[100 + tid];
        const float go = s_go[150 + tid];
        const float c2 = sigmoidf_(gi) * tanhf(gc);
        s_feat[100 + tid] = sigmoidf_(go) * tanhf(c2);
    } else if (tid < 150) {
        const int t = tid - 50;        // 0..99 flattened (g,j)
        const int g = t / 10;
        const int j = t - g * 10;
        const int base = g * 40;
        const float gi = s_gg[base + j];
        const float gf = s_gg[base + 10 + j];
        const float gc = s_gg[base + 20 + j];
        const float go = s_gg[base + 30 + j];
        const float c2 = sigmoidf_(gf) * s_c0[t] + sigmoidf_(gi) * tanhf(gc);
        s_feat[t] = sigmoidf_(go) * tanhf(c2);
    }
    __syncthreads();

    // ---- phase 3: dense 75x150, warp-per-output (coalesced W1 reads) ----
    const int warp = tid >> 5;
    const int lane = tid & 31;
    for (int m = warp; m < 75; m += 8) {
        const float* __restrict__ wr = W1 + m * 150;
        float acc = 0.0f;
        #pragma unroll
        for (int i = lane; i < 150; i += 32) acc = fmaf(wr[i], s_feat[i], acc);
        #pragma unroll
        for (int off = 16; off; off >>= 1)
            acc += __shfl_xor_sync(0xffffffffu, acc, off);
        if (lane == 0) s_hid[m] = acc + b1[m];
    }
    __syncthreads();

    // ---- phase 4: out = W2 . hid + b2 (warp 0) ----
    if (warp == 0) {
        float acc = 0.0f;
        for (int m = lane; m < 75; m += 32) acc = fmaf(W2[m], s_hid[m], acc);
        #pragma unroll
        for (int off = 16; off; off >>= 1)
            acc += __shfl_xor_sync(0xffffffffu, acc, off);
        if (lane == 0) out[0] = acc + b2[0];
    }
}

extern "C" void kernel_launch(void* const* d_in, const int* in_sizes, int n_in,
                              void* d_out, int out_size)
{
    const float* x        = (const float*)d_in[0];
    const float* h0_gen   = (const float*)d_in[1];
    const float* c0_gen   = (const float*)d_in[2];
    const float* W_ih_opp = (const float*)d_in[3];
    // d_in[4] = W_hh_opp — unused (zero initial state)
    const float* b_ih_opp = (const float*)d_in[5];
    const float* b_hh_opp = (const float*)d_in[6];
    const float* W_ih_gen = (const float*)d_in[7];
    const float* W_hh_gen = (const float*)d_in[8];
    const float* b_ih_gen = (const float*)d_in[9];
    const float* b_hh_gen = (const float*)d_in[10];
    const float* W1       = (const float*)d_in[11];
    const float* b1       = (const float*)d_in[12];
    const float* W2       = (const float*)d_in[13];
    const float* b2       = (const float*)d_in[14];
    float* out = (float*)d_out;

    net_kernel<<<1, 256>>>(x, h0_gen, c0_gen, W_ih_opp, b_ih_opp, b_hh_opp,
                           W_ih_gen, W_hh_gen, b_ih_gen, b_hh_gen,
                           W1, b1, W2, b2, out);
}

// round 2
// speedup vs baseline: 1.5955x; 1.5955x over previous
#include <cuda_runtime.h>

// Net_32521492365587 — tiny LSTM ensemble + dense decode, single scalar output.
// Single block, 256 threads, ALL global loads issued before the first barrier
// so the kernel pays ~one DRAM round-trip latency total.
//
// Inputs (metadata order):
//  0 x(8) 1 h0_gen(100) 2 c0_gen(100) 3 W_ih_opp(200,8) 4 W_hh_opp[UNUSED]
//  5 b_ih_opp(200) 6 b_hh_opp(200) 7 W_ih_gen(10,40,8) 8 W_hh_gen(10,40,10)
//  9 b_ih_gen(400) 10 b_hh_gen(400) 11 W1(75,150) 12 b1(75) 13 W2(75) 14 b2(1)

__device__ __forceinline__ float sigmoidf_(float v) {
    return 1.0f / (1.0f + __expf(-v));
}

__device__ __forceinline__ float warp_sum(float v) {
    #pragma unroll
    for (int off = 16; off; off >>= 1)
        v += __shfl_xor_sync(0xffffffffu, v, off);
    return v;
}

__global__ __launch_bounds__(256, 1)
void net_kernel(const float* __restrict__ x,
                const float* __restrict__ h0_gen,
                const float* __restrict__ c0_gen,
                const float* __restrict__ W_ih_opp,
                const float* __restrict__ b_ih_opp,
                const float* __restrict__ b_hh_opp,
                const float* __restrict__ W_ih_gen,
                const float* __restrict__ W_hh_gen,
                const float* __restrict__ b_ih_gen,
                const float* __restrict__ b_hh_gen,
                const float* __restrict__ W1,
                const float* __restrict__ b1,
                const float* __restrict__ W2,
                const float* __restrict__ b2,
                float* __restrict__ out)
{
    __shared__ float s_feat[152];  // [h_gen(100) | h_opp(50)], padded
    __shared__ float s_hid[76];

    const int tid  = threadIdx.x;
    const int warp = tid >> 5;
    const int lane = tid & 31;

    // ---------------- prefetch W1 / b1 (phase-3 pattern), all warps ----------
    // warp w handles rows m = w, w+8, ..., row as 75 float2; lane takes
    // float2 indices {lane, lane+32, lane+64(lane<11)}.
    float2 w1r[10][3];
    float  b1r[10];
    #pragma unroll
    for (int r = 0; r < 10; ++r) {
        const int m = warp + r * 8;
        if (m < 75) {
            const float2* __restrict__ row = reinterpret_cast<const float2*>(W1 + m * 150);
            w1r[r][0] = row[lane];
            w1r[r][1] = row[lane + 32];
            if (lane < 11) w1r[r][2] = row[lane + 64];
            b1r[r] = b1[m];
        } else {
            w1r[r][0] = w1r[r][1] = w1r[r][2] = make_float2(0.f, 0.f);
            b1r[r] = 0.f;
        }
    }

    // ---------------- prefetch W2 / b2 (warp 0) ------------------------------
    float w2r0 = 0.f, w2r1 = 0.f, w2r2 = 0.f, b2r = 0.f;
    if (warp == 0) {
        w2r0 = W2[lane];
        w2r1 = W2[lane + 32];
        if (lane + 64 < 75) w2r2 = W2[lane + 64];
        if (lane == 0) b2r = b2[0];
    }

    // ---------------- fused gates + activations (no staging barrier) --------
    if (tid < 100) {
        // gen lane: cell g, unit j
        const int g = tid / 10;
        const int j = tid - g * 10;

        const float4 xv0 = reinterpret_cast<const float4*>(x)[0];
        const float4 xv1 = reinterpret_cast<const float4*>(x)[1];
        float2 h2[5];
        const float2* __restrict__ h0p = reinterpret_cast<const float2*>(h0_gen + g * 10);
        #pragma unroll
        for (int k = 0; k < 5; ++k) h2[k] = h0p[k];
        const float c0v = c0_gen[tid];

        float gate[4];
        #pragma unroll
        for (int k = 0; k < 4; ++k) {
            const int row = g * 40 + k * 10 + j;
            const float4* __restrict__ wi = reinterpret_cast<const float4*>(W_ih_gen + row * 8);
            const float2* __restrict__ wh = reinterpret_cast<const float2*>(W_hh_gen + row * 10);
            float acc = b_ih_gen[row] + b_hh_gen[row];
            const float4 a = wi[0], b = wi[1];
            acc = fmaf(a.x, xv0.x, acc); acc = fmaf(a.y, xv0.y, acc);
            acc = fmaf(a.z, xv0.z, acc); acc = fmaf(a.w, xv0.w, acc);
            acc = fmaf(b.x, xv1.x, acc); acc = fmaf(b.y, xv1.y, acc);
            acc = fmaf(b.z, xv1.z, acc); acc = fmaf(b.w, xv1.w, acc);
            #pragma unroll
            for (int kk = 0; kk < 5; ++kk) {
                const float2 w = wh[kk];
                acc = fmaf(w.x, h2[kk].x, acc);
                acc = fmaf(w.y, h2[kk].y, acc);
            }
            gate[k] = acc;
        }
        // gate order i,f,g,o
        const float c2 = sigmoidf_(gate[1]) * c0v + sigmoidf_(gate[0]) * tanhf(gate[2]);
        s_feat[tid] = sigmoidf_(gate[3]) * tanhf(c2);
    } else if (tid < 150) {
        // opp lane o: zero initial state -> f-gate dead, c2 = sig(i)*tanh(g)
        const int o = tid - 100;
        const float4 xv0 = reinterpret_cast<const float4*>(x)[0];
        const float4 xv1 = reinterpret_cast<const float4*>(x)[1];
        const int rows[3] = { o, 100 + o, 150 + o };  // i, g, o rows
        float gv[3];
        #pragma unroll
        for (int k = 0; k < 3; ++k) {
            const int row = rows[k];
            const float4* __restrict__ w = reinterpret_cast<const float4*>(W_ih_opp + row * 8);
            float acc = b_ih_opp[row] + b_hh_opp[row];
            const float4 a = w[0], b = w[1];
            acc = fmaf(a.x, xv0.x, acc); acc = fmaf(a.y, xv0.y, acc);
            acc = fmaf(a.z, xv0.z, acc); acc = fmaf(a.w, xv0.w, acc);
            acc = fmaf(b.x, xv1.x, acc); acc = fmaf(b.y, xv1.y, acc);
            acc = fmaf(b.z, xv1.z, acc); acc = fmaf(b.w, xv1.w, acc);
            gv[k] = acc;
        }
        const float c2 = sigmoidf_(gv[0]) * tanhf(gv[1]);
        s_feat[100 + o] = sigmoidf_(gv[2]) * tanhf(c2);
    }
    __syncthreads();

    // ---------------- dense 75x150: warp-per-output, register weights -------
    const float2* __restrict__ sf2 = reinterpret_cast<const float2*>(s_feat);
    const float2 f0 = sf2[lane];
    const float2 f1 = sf2[lane + 32];
    float2 f2 = make_float2(0.f, 0.f);
    if (lane < 11) f2 = sf2[lane + 64];

    #pragma unroll
    for (int r = 0; r < 10; ++r) {
        const int m = warp + r * 8;
        if (m < 75) {
            float acc;
            acc = w1r[r][0].x * f0.x;
            acc = fmaf(w1r[r][0].y, f0.y, acc);
            acc = fmaf(w1r[r][1].x, f1.x, acc);
            acc = fmaf(w1r[r][1].y, f1.y, acc);
            acc = fmaf(w1r[r][2].x, f2.x, acc);
            acc = fmaf(w1r[r][2].y, f2.y, acc);
            acc = warp_sum(acc);
            if (lane == 0) s_hid[m] = acc + b1r[r];
        }
    }
    __syncthreads();

    // ---------------- out = W2 . hid + b2 (warp 0) ---------------------------
    if (warp == 0) {
        float acc = w2r0 * s_hid[lane];
        acc = fmaf(w2r1, s_hid[lane + 32], acc);
        if (lane + 64 < 75) acc = fmaf(w2r2, s_hid[lane + 64], acc);
        acc = warp_sum(acc);
        if (lane == 0) out[0] = acc + b2r;
    }
}

extern "C" void kernel_launch(void* const* d_in, const int* in_sizes, int n_in,
                              void* d_out, int out_size)
{
    const float* x        = (const float*)d_in[0];
    const float* h0_gen   = (const float*)d_in[1];
    const float* c0_gen   = (const float*)d_in[2];
    const float* W_ih_opp = (const float*)d_in[3];
    // d_in[4] = W_hh_opp — unused (zero initial state)
    const float* b_ih_opp = (const float*)d_in[5];
    const float* b_hh_opp = (const float*)d_in[6];
    const float* W_ih_gen = (const float*)d_in[7];
    const float* W_hh_gen = (const float*)d_in[8];
    const float* b_ih_gen = (const float*)d_in[9];
    const float* b_hh_gen = (const float*)d_in[10];
    const float* W1       = (const float*)d_in[11];
    const float* b1       = (const float*)d_in[12];
    const float* W2       = (const float*)d_in[13];
    const float* b2       = (const float*)d_in[14];
    float* out = (float*)d_out;

    net_kernel<<<1, 256>>>(x, h0_gen, c0_gen, W_ih_opp, b_ih_opp, b_hh_opp,
                           W_ih_gen, W_hh_gen, b_ih_gen, b_hh_gen,
                           W1, b1, W2, b2, out);
}

// round 3
// speedup vs baseline: 1.6250x; 1.0185x over previous
#include <cuda_runtime.h>

// Net_32521492365587 — tiny LSTM ensemble + dense decode, single scalar output.
//
// Key algebraic move: no nonlinearity between W1 and W2, so
//   out = W2·(W1·feat + b1) + b2 = (W1^T·W2)·feat + (W2·b1 + b2)
// v = W1^T·W2 (150,) and c = W2·b1+b2 depend only on weights, so dedicated
// warps compute them IN PARALLEL with the LSTM gate phase. After one barrier
// the tail is a single 150-dot + shuffle reduce + STG.
//
// Thread plan (384 threads, 12 warps):
//   tid   0..149 : gate lanes -> s_feat   (gen 0..99, opp 100..149)
//   tid 160..309 : v columns  -> s_v
//   warp 10      : scalar c   -> s_c
//   warp 11      : (post-bar) final dot -> out

__device__ __forceinline__ float sigmoidf_(float v) {
    return 1.0f / (1.0f + __expf(-v));
}

__device__ __forceinline__ float warp_sum(float v) {
    #pragma unroll
    for (int off = 16; off; off >>= 1)
        v += __shfl_xor_sync(0xffffffffu, v, off);
    return v;
}

__global__ __launch_bounds__(384, 1)
void net_kernel(const float* __restrict__ x,
                const float* __restrict__ h0_gen,
                const float* __restrict__ c0_gen,
                const float* __restrict__ W_ih_opp,
                const float* __restrict__ b_ih_opp,
                const float* __restrict__ b_hh_opp,
                const float* __restrict__ W_ih_gen,
                const float* __restrict__ W_hh_gen,
                const float* __restrict__ b_ih_gen,
                const float* __restrict__ b_hh_gen,
                const float* __restrict__ W1,
                const float* __restrict__ b1,
                const float* __restrict__ W2,
                const float* __restrict__ b2,
                float* __restrict__ out)
{
    __shared__ float s_feat[152];  // [h_gen(100) | h_opp(50)]
    __shared__ float s_v[152];     // W1^T @ W2
    __shared__ float s_c;          // W2.b1 + b2

    const int tid  = threadIdx.x;
    const int warp = tid >> 5;
    const int lane = tid & 31;

    if (tid < 100) {
        // ---- gen lane: cell g, unit j — all 4 gates fused per thread ----
        const int g = tid / 10;
        const int j = tid - g * 10;

        const float4 xv0 = reinterpret_cast<const float4*>(x)[0];
        const float4 xv1 = reinterpret_cast<const float4*>(x)[1];
        float2 h2[5];
        const float2* __restrict__ h0p = reinterpret_cast<const float2*>(h0_gen + g * 10);
        #pragma unroll
        for (int k = 0; k < 5; ++k) h2[k] = h0p[k];
        const float c0v = c0_gen[tid];

        float gate[4];
        #pragma unroll
        for (int k = 0; k < 4; ++k) {
            const int row = g * 40 + k * 10 + j;
            const float4* __restrict__ wi = reinterpret_cast<const float4*>(W_ih_gen + row * 8);
            const float2* __restrict__ wh = reinterpret_cast<const float2*>(W_hh_gen + row * 10);
            float acc = b_ih_gen[row] + b_hh_gen[row];
            const float4 a = wi[0], b = wi[1];
            acc = fmaf(a.x, xv0.x, acc); acc = fmaf(a.y, xv0.y, acc);
            acc = fmaf(a.z, xv0.z, acc); acc = fmaf(a.w, xv0.w, acc);
            acc = fmaf(b.x, xv1.x, acc); acc = fmaf(b.y, xv1.y, acc);
            acc = fmaf(b.z, xv1.z, acc); acc = fmaf(b.w, xv1.w, acc);
            #pragma unroll
            for (int kk = 0; kk < 5; ++kk) {
                const float2 w = wh[kk];
                acc = fmaf(w.x, h2[kk].x, acc);
                acc = fmaf(w.y, h2[kk].y, acc);
            }
            gate[k] = acc;
        }
        // gate order i,f,g,o
        const float c2 = sigmoidf_(gate[1]) * c0v + sigmoidf_(gate[0]) * tanhf(gate[2]);
        s_feat[tid] = sigmoidf_(gate[3]) * tanhf(c2);
    } else if (tid < 150) {
        // ---- opp lane: zero initial state -> f-gate dead ----
        const int o = tid - 100;
        const float4 xv0 = reinterpret_cast<const float4*>(x)[0];
        const float4 xv1 = reinterpret_cast<const float4*>(x)[1];
        const int rows[3] = { o, 100 + o, 150 + o };   // i, g, o rows
        float gv[3];
        #pragma unroll
        for (int k = 0; k < 3; ++k) {
            const int row = rows[k];
            const float4* __restrict__ w = reinterpret_cast<const float4*>(W_ih_opp + row * 8);
            float acc = b_ih_opp[row] + b_hh_opp[row];
            const float4 a = w[0], b = w[1];
            acc = fmaf(a.x, xv0.x, acc); acc = fmaf(a.y, xv0.y, acc);
            acc = fmaf(a.z, xv0.z, acc); acc = fmaf(a.w, xv0.w, acc);
            acc = fmaf(b.x, xv1.x, acc); acc = fmaf(b.y, xv1.y, acc);
            acc = fmaf(b.z, xv1.z, acc); acc = fmaf(b.w, xv1.w, acc);
            gv[k] = acc;
        }
        const float c2 = sigmoidf_(gv[0]) * tanhf(gv[1]);
        s_feat[100 + o] = sigmoidf_(gv[2]) * tanhf(c2);
    } else if (tid >= 160 && tid < 310) {
        // ---- v[i] = sum_m W2[m] * W1[m,i]  (coalesced across lanes per m) ----
        const int i = tid - 160;
        const float* __restrict__ w1c = W1 + i;
        float acc = 0.0f;
        #pragma unroll 15
        for (int m = 0; m < 75; ++m)
            acc = fmaf(__ldg(W2 + m), w1c[m * 150], acc);
        s_v[i] = acc;
    } else if (warp == 10) {
        // ---- c = W2.b1 + b2 ----
        float acc = 0.0f;
        #pragma unroll
        for (int m = lane; m < 75; m += 32)
            acc = fmaf(W2[m], b1[m], acc);
        acc = warp_sum(acc);
        if (lane == 0) s_c = acc + b2[0];
    }
    __syncthreads();

    // ---- tail: out = v.feat + c   (warp 11, cold until now) ----
    if (warp == 11) {
        float acc = 0.0f;
        #pragma unroll
        for (int i = lane; i < 150; i += 32)
            acc = fmaf(s_v[i], s_feat[i], acc);
        acc = warp_sum(acc);
        if (lane == 0) out[0] = acc + s_c;
    }
}

extern "C" void kernel_launch(void* const* d_in, const int* in_sizes, int n_in,
                              void* d_out, int out_size)
{
    const float* x        = (const float*)d_in[0];
    const float* h0_gen   = (const float*)d_in[1];
    const float* c0_gen   = (const float*)d_in[2];
    const float* W_ih_opp = (const float*)d_in[3];
    // d_in[4] = W_hh_opp — unused (zero initial state)
    const float* b_ih_opp = (const float*)d_in[5];
    const float* b_hh_opp = (const float*)d_in[6];
    const float* W_ih_gen = (const float*)d_in[7];
    const float* W_hh_gen = (const float*)d_in[8];
    const float* b_ih_gen = (const float*)d_in[9];
    const float* b_hh_gen = (const float*)d_in[10];
    const float* W1       = (const float*)d_in[11];
    const float* b1       = (const float*)d_in[12];
    const float* W2       = (const float*)d_in[13];
    const float* b2       = (const float*)d_in[14];
    float* out = (float*)d_out;

    net_kernel<<<1, 384>>>(x, h0_gen, c0_gen, W_ih_opp, b_ih_opp, b_hh_opp,
                           W_ih_gen, W_hh_gen, b_ih_gen, b_hh_gen,
                           W1, b1, W2, b2, out);
}

// round 4
// speedup vs baseline: 1.6402x; 1.0093x over previous
#include <cuda_runtime.h>

// Net_32521492365587 — tiny LSTM ensemble + dense decode, single scalar output.
//
// out = W2·(W1·feat + b1) + b2 = (W1^T·W2)·feat + (W2·b1 + b2)
// v = W1^T·W2 and c = W2·b1+b2 depend only on weights -> computed concurrently
// with the LSTM gate phase. Critical insight from R3: the kernel is bounded by
// the NUMBER OF SEQUENTIAL DRAM-LATENCY WAVES (~2us each, cold L1 + low clock),
// so the v reduction is split in half across 300 threads with FULL unroll so
// all loads are outstanding at once (1 wave, not 5).
//
// Thread plan (512 threads, 16 warps):
//   tid   0..149 : gate lanes -> s_feat (gen 0..99, opp 100..149)
//   tid 160..309 : v partial, m in [0,38)   -> s_v0
//   tid 320..469 : v partial, m in [38,75)  -> s_v1
//   warp 15      : c = W2.b1 + b2; post-bar final dot -> out

__device__ __forceinline__ float sigmoidf_(float v) {
    return 1.0f / (1.0f + __expf(-v));
}

__device__ __forceinline__ float warp_sum(float v) {
    #pragma unroll
    for (int off = 16; off; off >>= 1)
        v += __shfl_xor_sync(0xffffffffu, v, off);
    return v;
}

__global__ __launch_bounds__(512, 1)
void net_kernel(const float* __restrict__ x,
                const float* __restrict__ h0_gen,
                const float* __restrict__ c0_gen,
                const float* __restrict__ W_ih_opp,
                const float* __restrict__ b_ih_opp,
                const float* __restrict__ b_hh_opp,
                const float* __restrict__ W_ih_gen,
                const float* __restrict__ W_hh_gen,
                const float* __restrict__ b_ih_gen,
                const float* __restrict__ b_hh_gen,
                const float* __restrict__ W1,
                const float* __restrict__ b1,
                const float* __restrict__ W2,
                const float* __restrict__ b2,
                float* __restrict__ out)
{
    __shared__ float s_feat[152];
    __shared__ float s_v0[152];
    __shared__ float s_v1[152];
    __shared__ float s_c;

    const int tid  = threadIdx.x;
    const int warp = tid >> 5;
    const int lane = tid & 31;

    if (tid < 100) {
        // ---- gen lane: cell g, unit j — all 4 gates fused per thread ----
        const int g = tid / 10;
        const int j = tid - g * 10;

        const float4 xv0 = reinterpret_cast<const float4*>(x)[0];
        const float4 xv1 = reinterpret_cast<const float4*>(x)[1];
        float2 h2[5];
        const float2* __restrict__ h0p = reinterpret_cast<const float2*>(h0_gen + g * 10);
        #pragma unroll
        for (int k = 0; k < 5; ++k) h2[k] = h0p[k];
        const float c0v = c0_gen[tid];

        float gate[4];
        #pragma unroll
        for (int k = 0; k < 4; ++k) {
            const int row = g * 40 + k * 10 + j;
            const float4* __restrict__ wi = reinterpret_cast<const float4*>(W_ih_gen + row * 8);
            const float2* __restrict__ wh = reinterpret_cast<const float2*>(W_hh_gen + row * 10);
            float acc = b_ih_gen[row] + b_hh_gen[row];
            const float4 a = wi[0], b = wi[1];
            acc = fmaf(a.x, xv0.x, acc); acc = fmaf(a.y, xv0.y, acc);
            acc = fmaf(a.z, xv0.z, acc); acc = fmaf(a.w, xv0.w, acc);
            acc = fmaf(b.x, xv1.x, acc); acc = fmaf(b.y, xv1.y, acc);
            acc = fmaf(b.z, xv1.z, acc); acc = fmaf(b.w, xv1.w, acc);
            #pragma unroll
            for (int kk = 0; kk < 5; ++kk) {
                const float2 w = wh[kk];
                acc = fmaf(w.x, h2[kk].x, acc);
                acc = fmaf(w.y, h2[kk].y, acc);
            }
            gate[k] = acc;
        }
        // gate order i,f,g,o
        const float c2 = sigmoidf_(gate[1]) * c0v + sigmoidf_(gate[0]) * tanhf(gate[2]);
        s_feat[tid] = sigmoidf_(gate[3]) * tanhf(c2);
    } else if (tid < 150) {
        // ---- opp lane: zero initial state -> f-gate dead ----
        const int o = tid - 100;
        const float4 xv0 = reinterpret_cast<const float4*>(x)[0];
        const float4 xv1 = reinterpret_cast<const float4*>(x)[1];
        const int rows[3] = { o, 100 + o, 150 + o };   // i, g, o rows
        float gv[3];
        #pragma unroll
        for (int k = 0; k < 3; ++k) {
            const int row = rows[k];
            const float4* __restrict__ w = reinterpret_cast<const float4*>(W_ih_opp + row * 8);
            float acc = b_ih_opp[row] + b_hh_opp[row];
            const float4 a = w[0], b = w[1];
            acc = fmaf(a.x, xv0.x, acc); acc = fmaf(a.y, xv0.y, acc);
            acc = fmaf(a.z, xv0.z, acc); acc = fmaf(a.w, xv0.w, acc);
            acc = fmaf(b.x, xv1.x, acc); acc = fmaf(b.y, xv1.y, acc);
            acc = fmaf(b.z, xv1.z, acc); acc = fmaf(b.w, xv1.w, acc);
            gv[k] = acc;
        }
        const float c2 = sigmoidf_(gv[0]) * tanhf(gv[1]);
        s_feat[100 + o] = sigmoidf_(gv[2]) * tanhf(c2);
    } else if (tid >= 160 && tid < 310) {
        // ---- v-half0: v0[i] = sum_{m=0}^{37} W2[m] * W1[m,i], FULL unroll ----
        const int i = tid - 160;
        const float* __restrict__ w1c = W1 + i;
        float acc = 0.0f;
        #pragma unroll
        for (int m = 0; m < 38; ++m)
            acc = fmaf(__ldg(W2 + m), w1c[m * 150], acc);
        s_v0[i] = acc;
    } else if (tid >= 320 && tid < 470) {
        // ---- v-half1: v1[i] = sum_{m=38}^{74} W2[m] * W1[m,i], FULL unroll ---
        const int i = tid - 320;
        const float* __restrict__ w1c = W1 + 38 * 150 + i;
        float acc = 0.0f;
        #pragma unroll
        for (int m = 0; m < 37; ++m)
            acc = fmaf(__ldg(W2 + 38 + m), w1c[m * 150], acc);
        s_v1[i] = acc;
    } else if (warp == 15) {
        // ---- c = W2.b1 + b2 ----
        float acc = 0.0f;
        #pragma unroll
        for (int m = lane; m < 75; m += 32)
            acc = fmaf(W2[m], b1[m], acc);
        acc = warp_sum(acc);
        if (lane == 0) s_c = acc + b2[0];
    }
    __syncthreads();

    // ---- tail: out = (v0+v1).feat + c  (warp 15) ----
    if (warp == 15) {
        float acc = 0.0f;
        #pragma unroll
        for (int i = lane; i < 150; i += 32)
            acc = fmaf(s_v0[i] + s_v1[i], s_feat[i], acc);
        acc = warp_sum(acc);
        if (lane == 0) out[0] = acc + s_c;
    }
}

extern "C" void kernel_launch(void* const* d_in, const int* in_sizes, int n_in,
                              void* d_out, int out_size)
{
    const float* x        = (const float*)d_in[0];
    const float* h0_gen   = (const float*)d_in[1];
    const float* c0_gen   = (const float*)d_in[2];
    const float* W_ih_opp = (const float*)d_in[3];
    // d_in[4] = W_hh_opp — unused (zero initial state)
    const float* b_ih_opp = (const float*)d_in[5];
    const float* b_hh_opp = (const float*)d_in[6];
    const float* W_ih_gen = (const float*)d_in[7];
    const float* W_hh_gen = (const float*)d_in[8];
    const float* b_ih_gen = (const float*)d_in[9];
    const float* b_hh_gen = (const float*)d_in[10];
    const float* W1       = (const float*)d_in[11];
    const float* b1       = (const float*)d_in[12];
    const float* W2       = (const float*)d_in[13];
    const float* b2       = (const float*)d_in[14];
    float* out = (float*)d_out;

    net_kernel<<<1, 512>>>(x, h0_gen, c0_gen, W_ih_opp, b_ih_opp, b_hh_opp,
                           W_ih_gen, W_hh_gen, b_ih_gen, b_hh_gen,
                           W1, b1, W2, b2, out);
}

// round 5
// speedup vs baseline: 1.7206x; 1.0490x over previous
#include <cuda_runtime.h>

// Net_32521492365587 — tiny LSTM ensemble + dense decode, single scalar output.
//
// out = W2·(W1·feat + b1) + b2 = (W1^T·W2)·feat + (W2·b1 + b2)
// v = W1^T·W2 and c = W2·b1+b2 depend only on weights -> computed concurrently
// with the LSTM gate phase (one barrier total).
//
// R5 focus: the kernel is ~2K cycles at a low clock; critical path = gate-lane
// math. Library tanhf (accurate, branchy, divergent) replaced by the MUFU
// identity tanh(x) = 1 - 2/(e^(2x)+1)  (EX2 + RCP, rel err ~1e-6).
// Scalar c stays in the tail warp's registers (no smem round trip).
//
// Thread plan (512 threads, 16 warps):
//   tid   0..149 : gate lanes -> s_feat (gen 0..99, opp 100..149)
//   tid 160..309 : v partial, m in [0,38)   -> s_v0
//   tid 320..469 : v partial, m in [38,75)  -> s_v1
//   warp 15      : c = W2.b1 + b2 (register); post-bar final dot -> out

__device__ __forceinline__ float sigmoid_f(float v) {
    // 1/(1+e^-v) via MUFU EX2+RCP, rel err ~1e-7
    return 1.0f / (1.0f + __expf(-v));
}

__device__ __forceinline__ float tanh_f(float v) {
    // tanh(v) = 1 - 2/(e^(2v)+1); MUFU EX2 + RCP, rel err ~1e-6, branch-free
    const float e = __expf(2.0f * v);
    return fmaf(-2.0f, __frcp_rn(e + 1.0f), 1.0f);
}

__device__ __forceinline__ float warp_sum(float v) {
    #pragma unroll
    for (int off = 16; off; off >>= 1)
        v += __shfl_xor_sync(0xffffffffu, v, off);
    return v;
}

__global__ __launch_bounds__(512, 1)
void net_kernel(const float* __restrict__ x,
                const float* __restrict__ h0_gen,
                const float* __restrict__ c0_gen,
                const float* __restrict__ W_ih_opp,
                const float* __restrict__ b_ih_opp,
                const float* __restrict__ b_hh_opp,
                const float* __restrict__ W_ih_gen,
                const float* __restrict__ W_hh_gen,
                const float* __restrict__ b_ih_gen,
                const float* __restrict__ b_hh_gen,
                const float* __restrict__ W1,
                const float* __restrict__ b1,
                const float* __restrict__ W2,
                const float* __restrict__ b2,
                float* __restrict__ out)
{
    __shared__ float s_feat[152];
    __shared__ float s_v0[152];
    __shared__ float s_v1[152];

    const int tid  = threadIdx.x;
    const int warp = tid >> 5;
    const int lane = tid & 31;

    float c_reg = 0.0f;   // live only in warp 15

    if (tid < 100) {
        // ---- gen lane: cell g, unit j — all 4 gates fused per thread ----
        const int g = tid / 10;
        const int j = tid - g * 10;

        const float4 xv0 = reinterpret_cast<const float4*>(x)[0];
        const float4 xv1 = reinterpret_cast<const float4*>(x)[1];
        float2 h2[5];
        const float2* __restrict__ h0p = reinterpret_cast<const float2*>(h0_gen + g * 10);
        #pragma unroll
        for (int k = 0; k < 5; ++k) h2[k] = h0p[k];
        const float c0v = c0_gen[tid];

        float gate[4];
        #pragma unroll
        for (int k = 0; k < 4; ++k) {
            const int row = g * 40 + k * 10 + j;
            const float4* __restrict__ wi = reinterpret_cast<const float4*>(W_ih_gen + row * 8);
            const float2* __restrict__ wh = reinterpret_cast<const float2*>(W_hh_gen + row * 10);
            float acc = b_ih_gen[row] + b_hh_gen[row];
            const float4 a = wi[0], b = wi[1];
            acc = fmaf(a.x, xv0.x, acc); acc = fmaf(a.y, xv0.y, acc);
            acc = fmaf(a.z, xv0.z, acc); acc = fmaf(a.w, xv0.w, acc);
            acc = fmaf(b.x, xv1.x, acc); acc = fmaf(b.y, xv1.y, acc);
            acc = fmaf(b.z, xv1.z, acc); acc = fmaf(b.w, xv1.w, acc);
            #pragma unroll
            for (int kk = 0; kk < 5; ++kk) {
                const float2 w = wh[kk];
                acc = fmaf(w.x, h2[kk].x, acc);
                acc = fmaf(w.y, h2[kk].y, acc);
            }
            gate[k] = acc;
        }
        // gate order i,f,g,o
        const float c2 = sigmoid_f(gate[1]) * c0v + sigmoid_f(gate[0]) * tanh_f(gate[2]);
        s_feat[tid] = sigmoid_f(gate[3]) * tanh_f(c2);
    } else if (tid < 150) {
        // ---- opp lane: zero initial state -> f-gate dead ----
        const int o = tid - 100;
        const float4 xv0 = reinterpret_cast<const float4*>(x)[0];
        const float4 xv1 = reinterpret_cast<const float4*>(x)[1];
        const int rows[3] = { o, 100 + o, 150 + o };   // i, g, o rows
        float gv[3];
        #pragma unroll
        for (int k = 0; k < 3; ++k) {
            const int row = rows[k];
            const float4* __restrict__ w = reinterpret_cast<const float4*>(W_ih_opp + row * 8);
            float acc = b_ih_opp[row] + b_hh_opp[row];
            const float4 a = w[0], b = w[1];
            acc = fmaf(a.x, xv0.x, acc); acc = fmaf(a.y, xv0.y, acc);
            acc = fmaf(a.z, xv0.z, acc); acc = fmaf(a.w, xv0.w, acc);
            acc = fmaf(b.x, xv1.x, acc); acc = fmaf(b.y, xv1.y, acc);
            acc = fmaf(b.z, xv1.z, acc); acc = fmaf(b.w, xv1.w, acc);
            gv[k] = acc;
        }
        const float c2 = sigmoid_f(gv[0]) * tanh_f(gv[1]);
        s_feat[100 + o] = sigmoid_f(gv[2]) * tanh_f(c2);
    } else if (tid >= 160 && tid < 310) {
        // ---- v-half0: v0[i] = sum_{m=0}^{37} W2[m]*W1[m,i], FULL unroll ----
        const int i = tid - 160;
        const float* __restrict__ w1c = W1 + i;
        float acc = 0.0f;
        #pragma unroll
        for (int m = 0; m < 38; ++m)
            acc = fmaf(__ldg(W2 + m), w1c[m * 150], acc);
        s_v0[i] = acc;
    } else if (tid >= 320 && tid < 470) {
        // ---- v-half1: v1[i] = sum_{m=38}^{74} W2[m]*W1[m,i], FULL unroll ----
        const int i = tid - 320;
        const float* __restrict__ w1c = W1 + 38 * 150 + i;
        float acc = 0.0f;
        #pragma unroll
        for (int m = 0; m < 37; ++m)
            acc = fmaf(__ldg(W2 + 38 + m), w1c[m * 150], acc);
        s_v1[i] = acc;
    } else if (warp == 15) {
        // ---- c = W2.b1 + b2 : kept in registers of the tail warp ----
        float acc = 0.0f;
        #pragma unroll
        for (int m = lane; m < 75; m += 32)
            acc = fmaf(W2[m], b1[m], acc);
        c_reg = warp_sum(acc) + __ldg(b2);   // all lanes hold total
    }
    __syncthreads();

    // ---- tail: out = (v0+v1).feat + c  (warp 15) ----
    if (warp == 15) {
        float acc = 0.0f;
        #pragma unroll
        for (int i = lane; i < 150; i += 32)
            acc = fmaf(s_v0[i] + s_v1[i], s_feat[i], acc);
        acc = warp_sum(acc);
        if (lane == 0) out[0] = acc + c_reg;
    }
}

extern "C" void kernel_launch(void* const* d_in, const int* in_sizes, int n_in,
                              void* d_out, int out_size)
{
    const float* x        = (const float*)d_in[0];
    const float* h0_gen   = (const float*)d_in[1];
    const float* c0_gen   = (const float*)d_in[2];
    const float* W_ih_opp = (const float*)d_in[3];
    // d_in[4] = W_hh_opp — unused (zero initial state)
    const float* b_ih_opp = (const float*)d_in[5];
    const float* b_hh_opp = (const float*)d_in[6];
    const float* W_ih_gen = (const float*)d_in[7];
    const float* W_hh_gen = (const float*)d_in[8];
    const float* b_ih_gen = (const float*)d_in[9];
    const float* b_hh_gen = (const float*)d_in[10];
    const float* W1       = (const float*)d_in[11];
    const float* b1       = (const float*)d_in[12];
    const float* W2       = (const float*)d_in[13];
    const float* b2       = (const float*)d_in[14];
    float* out = (float*)d_out;

    net_kernel<<<1, 512>>>(x, h0_gen, c0_gen, W_ih_opp, b_ih_opp, b_hh_opp,
                           W_ih_gen, W_hh_gen, b_ih_gen, b_hh_gen,
                           W1, b1, W2, b2, out);
}